// round 1
// baseline (speedup 1.0000x reference)
#include <cuda_runtime.h>
#include <math.h>

#define NB 8
#define DD 128
#define HW 1600
#define CC 1444

typedef unsigned long long ull;

// -------- scratch (static device arrays; no allocs allowed) --------
__device__ __align__(16) float d_bg[NB * HW * DD];          //  6.6 MB
__device__ __align__(16) float d_M[20480000];               // 81.9 MB  NB*HW*HW
__device__ __align__(16) float d_CA[18483200];              // 73.9 MB  NB*HW*CC
__device__ __align__(16) float d_T[20480000];               // 81.9 MB  NB*HW*HW
__device__ __align__(16) float d_Y[NB * HW * DD];           //  6.6 MB
__device__ float d_ng[NB * HW];
__device__ float d_k1d[NB * CC];
__device__ float d_wwd[NB * HW];

#define FMA2(acc, a, b) asm("fma.rn.f32x2 %0, %1, %2, %0;" : "+l"(acc) : "l"(a), "l"(b))
#define PACKD(dst, x)   asm("mov.b64 %0, {%1, %1};" : "=l"(dst) : "f"(x))
#define UNPK(lo, hi, v) asm("mov.b64 {%0, %1}, %2;" : "=f"(lo), "=f"(hi) : "l"(v))

// ---------------- prep1: bg = g*m, per-pixel |g|^2 ----------------
__global__ __launch_bounds__(128) void k_prep1(const float* __restrict__ g,
                                               const float* __restrict__ mask) {
    int p = blockIdx.x;              // 0..NB*HW-1
    int d = threadIdx.x;             // 128
    size_t gi = (size_t)p * DD + d;
    float gv = g[gi];
    float m = mask[p];
    d_bg[gi] = gv * m;
    float s = gv * gv;
#pragma unroll
    for (int o = 16; o; o >>= 1) s += __shfl_xor_sync(0xffffffffu, s, o);
    __shared__ float red[4];
    if ((d & 31) == 0) red[d >> 5] = s;
    __syncthreads();
    if (d == 0) d_ng[p] = red[0] + red[1] + red[2] + red[3];
}

// ---------------- prep2: k1d (patch norms of bg), wwd (padded window norms of g) ----
__global__ __launch_bounds__(256) void k_prep2(const float* __restrict__ mask) {
    int b = blockIdx.x;
    __shared__ float ng[HW];
    __shared__ float ms[HW];
    for (int i = threadIdx.x; i < HW; i += 256) {
        ng[i] = d_ng[b * HW + i];
        ms[i] = mask[b * HW + i];
    }
    __syncthreads();
    for (int c = threadIdx.x; c < CC; c += 256) {
        int i = c / 38, j = c - i * 38;
        float s = 0.f;
#pragma unroll
        for (int dy = 0; dy < 3; dy++)
#pragma unroll
            for (int dx = 0; dx < 3; dx++) {
                int q = (i + dy) * 40 + (j + dx);
                s += ng[q] * ms[q];     // n_bg = |g|^2 * m exactly (m in {0,1})
            }
        d_k1d[b * CC + c] = s;
    }
    for (int l = threadIdx.x; l < HW; l += 256) {
        int y = l / 40, x = l - y * 40;
        float s = 0.f;
#pragma unroll
        for (int oy = -1; oy <= 1; oy++)
#pragma unroll
            for (int ox = -1; ox <= 1; ox++) {
                int yy = y + oy, xx = x + ox;
                if (yy >= 0 && yy < 40 && xx >= 0 && xx < 40) s += ng[yy * 40 + xx];
            }
        d_wwd[b * HW + l] = s;
    }
}

// ---------------- GEMM1: M = g @ bg^T  (per batch 1600x1600, K=128) ----------------
// tile 64x64, 128 threads, 8x4 microtile, f32x2 (pair along rows, B duplicated in smem)
__global__ __launch_bounds__(128) void k_gemm1(const float* __restrict__ g) {
    int b = blockIdx.z;
    int bx = blockIdx.x, by = blockIdx.y;
    __shared__ float As[16][64];
    __shared__ float Bd[16][128];   // duplicated pairs
    const float* A = g + ((size_t)b * HW + by * 64) * DD;
    const float* B = d_bg + ((size_t)b * HW + bx * 64) * DD;
    int t = threadIdx.x;
    int tx = t & 15, ty = t >> 4;     // ty 0..7
    int r0 = ty * 8, c0 = tx * 4;
    int lr = t >> 1;                  // 0..63 (load row)
    int ls = (t & 1) * 2;             // seg base 0 or 2

    ull acc[4][4];
#pragma unroll
    for (int i = 0; i < 4; i++)
#pragma unroll
        for (int j = 0; j < 4; j++) acc[i][j] = 0ull;

    for (int k0 = 0; k0 < DD; k0 += 16) {
        float4 a0 = *(const float4*)(A + (size_t)lr * DD + k0 + ls * 4);
        float4 a1 = *(const float4*)(A + (size_t)lr * DD + k0 + ls * 4 + 4);
        float4 b0 = *(const float4*)(B + (size_t)lr * DD + k0 + ls * 4);
        float4 b1 = *(const float4*)(B + (size_t)lr * DD + k0 + ls * 4 + 4);
        __syncthreads();
        As[ls * 4 + 0][lr] = a0.x; As[ls * 4 + 1][lr] = a0.y;
        As[ls * 4 + 2][lr] = a0.z; As[ls * 4 + 3][lr] = a0.w;
        As[ls * 4 + 4][lr] = a1.x; As[ls * 4 + 5][lr] = a1.y;
        As[ls * 4 + 6][lr] = a1.z; As[ls * 4 + 7][lr] = a1.w;
        ull pv;
        PACKD(pv, b0.x); *(ull*)&Bd[ls * 4 + 0][2 * lr] = pv;
        PACKD(pv, b0.y); *(ull*)&Bd[ls * 4 + 1][2 * lr] = pv;
        PACKD(pv, b0.z); *(ull*)&Bd[ls * 4 + 2][2 * lr] = pv;
        PACKD(pv, b0.w); *(ull*)&Bd[ls * 4 + 3][2 * lr] = pv;
        PACKD(pv, b1.x); *(ull*)&Bd[ls * 4 + 4][2 * lr] = pv;
        PACKD(pv, b1.y); *(ull*)&Bd[ls * 4 + 5][2 * lr] = pv;
        PACKD(pv, b1.z); *(ull*)&Bd[ls * 4 + 6][2 * lr] = pv;
        PACKD(pv, b1.w); *(ull*)&Bd[ls * 4 + 7][2 * lr] = pv;
        __syncthreads();
#pragma unroll
        for (int kk = 0; kk < 16; kk++) {
            ulonglong2 av  = *(const ulonglong2*)&As[kk][r0];
            ulonglong2 av2 = *(const ulonglong2*)&As[kk][r0 + 4];
            ulonglong2 bv  = *(const ulonglong2*)&Bd[kk][2 * c0];
            ulonglong2 bv2 = *(const ulonglong2*)&Bd[kk][2 * c0 + 4];
            ull ap[4] = {av.x, av.y, av2.x, av2.y};
            ull bp[4] = {bv.x, bv.y, bv2.x, bv2.y};
#pragma unroll
            for (int i = 0; i < 4; i++)
#pragma unroll
                for (int j = 0; j < 4; j++) FMA2(acc[i][j], ap[i], bp[j]);
        }
    }
    float* Mo = d_M + (size_t)b * HW * HW;
    int col = bx * 64 + c0;
#pragma unroll
    for (int i = 0; i < 4; i++) {
        float lo0, hi0, lo1, hi1, lo2, hi2, lo3, hi3;
        UNPK(lo0, hi0, acc[i][0]); UNPK(lo1, hi1, acc[i][1]);
        UNPK(lo2, hi2, acc[i][2]); UNPK(lo3, hi3, acc[i][3]);
        int row = by * 64 + r0 + 2 * i;
        *(float4*)&Mo[(size_t)row * HW + col]       = make_float4(lo0, lo1, lo2, lo3);
        *(float4*)&Mo[(size_t)(row + 1) * HW + col] = make_float4(hi0, hi1, hi2, hi3);
    }
}

// ---------------- block reductions ----------------
__device__ __forceinline__ float bsum(float v, volatile float* red) {
#pragma unroll
    for (int o = 16; o; o >>= 1) v += __shfl_xor_sync(0xffffffffu, v, o);
    int lane = threadIdx.x & 31;
    if (lane == 0) red[threadIdx.x >> 5] = v;
    __syncthreads();
    if (threadIdx.x < 32) {
        v = (lane < 8) ? red[lane] : 0.f;
#pragma unroll
        for (int o = 4; o; o >>= 1) v += __shfl_xor_sync(0xffffffffu, v, o);
        if (lane == 0) red[0] = v;
    }
    __syncthreads();
    float r = red[0];
    __syncthreads();
    return r;
}

__device__ __forceinline__ float bmax(float v, volatile float* red) {
#pragma unroll
    for (int o = 16; o; o >>= 1) v = fmaxf(v, __shfl_xor_sync(0xffffffffu, v, o));
    int lane = threadIdx.x & 31;
    if (lane == 0) red[threadIdx.x >> 5] = v;
    __syncthreads();
    if (threadIdx.x < 32) {
        v = (lane < 8) ? red[lane] : -1e30f;
#pragma unroll
        for (int o = 4; o; o >>= 1) v = fmaxf(v, __shfl_xor_sync(0xffffffffu, v, o));
        if (lane == 0) red[0] = v;
    }
    __syncthreads();
    float r = red[0];
    __syncthreads();
    return r;
}

// ---------------- k3: cs-from-M gather + distance + row softmax -> CA ----------------
__global__ __launch_bounds__(256) void k3_softmax() {
    int b = blockIdx.x / HW;
    int loc = blockIdx.x - b * HW;
    int py = loc / 40, px = loc - py * 40;
    __shared__ float ds[CC];
    __shared__ float red[8];

    const float* Mb = d_M + (size_t)b * HW * HW;
    const float* rows[9];
    bool rv[9];
#pragma unroll
    for (int k = 0; k < 9; k++) {
        int oy = k / 3 - 1, ox = k % 3 - 1;
        int y = py + oy, x = px + ox;
        bool v = (y >= 0 && y < 40 && x >= 0 && x < 40);
        rv[k] = v;
        rows[k] = Mb + (size_t)(v ? (y * 40 + x) : 0) * HW;
    }
    float wwd = d_wwd[b * HW + loc];
    const float* k1 = d_k1d + b * CC;

    for (int c = threadIdx.x; c < CC; c += 256) {
        int i = c / 38, j = c - i * 38;
        int qy = i + 1, qx = j + 1;
        float cs = 0.f;
#pragma unroll
        for (int k = 0; k < 9; k++) {
            int oy = k / 3 - 1, ox = k % 3 - 1;
            if (rv[k]) cs += rows[k][(qy + oy) * 40 + (qx + ox)];
        }
        ds[c] = k1[c] + wwd - 2.f * cs;
    }
    __syncthreads();

    float s = 0.f;
    for (int c = threadIdx.x; c < CC; c += 256) s += ds[c];
    float mu = bsum(s, red) * (1.f / CC);

    float s2 = 0.f;
    for (int c = threadIdx.x; c < CC; c += 256) { float d0 = ds[c] - mu; s2 += d0 * d0; }
    float sd = sqrtf(bsum(s2, red) * (1.f / CC));
    float inv = 1.f / sd;

    float mx = -1e30f;
    for (int c = threadIdx.x; c < CC; c += 256) {
        float z = -50.f * tanhf((ds[c] - mu) * inv);
        ds[c] = z;
        mx = fmaxf(mx, z);
    }
    __syncthreads();
    mx = bmax(mx, red);

    float es = 0.f;
    for (int c = threadIdx.x; c < CC; c += 256) {
        float e = expf(ds[c] - mx);
        ds[c] = e;
        es += e;
    }
    __syncthreads();
    float itot = 1.f / bsum(es, red);

    float* car = d_CA + ((size_t)b * HW + loc) * CC;
    for (int c = threadIdx.x; c < CC; c += 256) car[c] = ds[c] * itot;
}

// ---------------- k4: build T[p][q] = sum_off ca[p-off][c(q-off)] ----------------
__global__ __launch_bounds__(256) void k4_buildT() {
    int b = blockIdx.x / HW;
    int p = blockIdx.x - b * HW;
    int py = p / 40, px = p - py * 40;
    const float* cab = d_CA + (size_t)b * HW * CC;
    const float* rows[9];
    bool rv[9];
#pragma unroll
    for (int k = 0; k < 9; k++) {
        int oy = k / 3 - 1, ox = k % 3 - 1;
        int ly = py - oy, lx = px - ox;
        bool v = (ly >= 0 && ly < 40 && lx >= 0 && lx < 40);
        rv[k] = v;
        rows[k] = cab + (size_t)(v ? (ly * 40 + lx) : 0) * CC;
    }
    float* trow = d_T + ((size_t)b * HW + p) * HW;
    for (int q = threadIdx.x; q < HW; q += 256) {
        int qy = q / 40, qx = q - qy * 40;
        float tsum = 0.f;
#pragma unroll
        for (int k = 0; k < 9; k++) {
            int oy = k / 3 - 1, ox = k % 3 - 1;
            int cy = qy - oy - 1, cx = qx - ox - 1;
            if (rv[k] && (unsigned)cy < 38u && (unsigned)cx < 38u)
                tsum += rows[k][cy * 38 + cx];
        }
        trow[q] = tsum;
    }
}

// ---------------- GEMM2: Y = T @ bg  (per batch 1600x128, K=1600) ----------------
// tile 64x128, 256 threads, 8x4 microtile, f32x2
__global__ __launch_bounds__(256) void k_gemm2() {
    int b = blockIdx.y;
    int bx = blockIdx.x;     // M tile (25)
    __shared__ float Ts[16][64];
    __shared__ float Bd[16][256];   // 128 cols duplicated
    const float* Trow = d_T + (size_t)b * HW * HW + (size_t)(bx * 64) * HW;
    const float* Bg = d_bg + (size_t)b * HW * DD;
    int t = threadIdx.x;
    int tx = t & 31, ty = t >> 5;     // tx 0..31 (cols c0=tx*4), ty 0..7 (rows r0=ty*8)
    int r0 = ty * 8, c0 = tx * 4;
    int alr = t >> 2, als = t & 3;    // A load: row 0..63, seg 0..3
    int blr = t >> 4, blc = (t & 15) * 8;  // B load: k-row 0..15, col base

    ull acc[4][4];
#pragma unroll
    for (int i = 0; i < 4; i++)
#pragma unroll
        for (int j = 0; j < 4; j++) acc[i][j] = 0ull;

    for (int k0 = 0; k0 < HW; k0 += 16) {
        float4 av = *(const float4*)(Trow + (size_t)alr * HW + k0 + als * 4);
        float4 b0 = *(const float4*)(Bg + (size_t)(k0 + blr) * DD + blc);
        float4 b1 = *(const float4*)(Bg + (size_t)(k0 + blr) * DD + blc + 4);
        __syncthreads();
        Ts[als * 4 + 0][alr] = av.x; Ts[als * 4 + 1][alr] = av.y;
        Ts[als * 4 + 2][alr] = av.z; Ts[als * 4 + 3][alr] = av.w;
        ull pv;
        PACKD(pv, b0.x); *(ull*)&Bd[blr][2 * blc + 0]  = pv;
        PACKD(pv, b0.y); *(ull*)&Bd[blr][2 * blc + 2]  = pv;
        PACKD(pv, b0.z); *(ull*)&Bd[blr][2 * blc + 4]  = pv;
        PACKD(pv, b0.w); *(ull*)&Bd[blr][2 * blc + 6]  = pv;
        PACKD(pv, b1.x); *(ull*)&Bd[blr][2 * blc + 8]  = pv;
        PACKD(pv, b1.y); *(ull*)&Bd[blr][2 * blc + 10] = pv;
        PACKD(pv, b1.z); *(ull*)&Bd[blr][2 * blc + 12] = pv;
        PACKD(pv, b1.w); *(ull*)&Bd[blr][2 * blc + 14] = pv;
        __syncthreads();
#pragma unroll
        for (int kk = 0; kk < 16; kk++) {
            ulonglong2 a1 = *(const ulonglong2*)&Ts[kk][r0];
            ulonglong2 a2 = *(const ulonglong2*)&Ts[kk][r0 + 4];
            ulonglong2 v1 = *(const ulonglong2*)&Bd[kk][2 * c0];
            ulonglong2 v2 = *(const ulonglong2*)&Bd[kk][2 * c0 + 4];
            ull ap[4] = {a1.x, a1.y, a2.x, a2.y};
            ull bp[4] = {v1.x, v1.y, v2.x, v2.y};
#pragma unroll
            for (int i = 0; i < 4; i++)
#pragma unroll
                for (int j = 0; j < 4; j++) FMA2(acc[i][j], ap[i], bp[j]);
        }
    }
    float* Yo = d_Y + (size_t)b * HW * DD;
#pragma unroll
    for (int i = 0; i < 4; i++) {
        float lo0, hi0, lo1, hi1, lo2, hi2, lo3, hi3;
        UNPK(lo0, hi0, acc[i][0]); UNPK(lo1, hi1, acc[i][1]);
        UNPK(lo2, hi2, acc[i][2]); UNPK(lo3, hi3, acc[i][3]);
        int row = bx * 64 + r0 + 2 * i;
        *(float4*)&Yo[(size_t)row * DD + c0]       = make_float4(lo0, lo1, lo2, lo3);
        *(float4*)&Yo[(size_t)(row + 1) * DD + c0] = make_float4(hi0, hi1, hi2, hi3);
    }
}

// ---------------- k5: acl combine + concat + 1x1 conv + ELU ----------------
__global__ __launch_bounds__(128) void k5_final(const float* __restrict__ g,
                                                const float* __restrict__ mask,
                                                const float* __restrict__ Wm,
                                                const float* __restrict__ bias,
                                                float* __restrict__ out) {
    int b = blockIdx.x / 50;
    int p0 = (blockIdx.x % 50) * 32;
    int d = threadIdx.x;
    __shared__ float con[32][256];

    for (int pp = 0; pp < 32; pp++) {
        int p = p0 + pp;
        size_t gi = ((size_t)b * HW + p) * DD + d;
        float gv = g[gi];
        float m = mask[b * HW + p];
        float acl = d_bg[gi] + (d_Y[gi] * (1.f / 9.f)) * (1.f - m);
        con[pp][d] = gv;
        con[pp][128 + d] = acl;
    }
    __syncthreads();

    float acc[32];
    float bv = bias[d];
#pragma unroll
    for (int pp = 0; pp < 32; pp++) acc[pp] = bv;

    for (int k4 = 0; k4 < 256; k4 += 4) {
        float w0 = Wm[(k4 + 0) * DD + d];
        float w1 = Wm[(k4 + 1) * DD + d];
        float w2 = Wm[(k4 + 2) * DD + d];
        float w3 = Wm[(k4 + 3) * DD + d];
#pragma unroll
        for (int pp = 0; pp < 32; pp++) {
            float4 cv = *(const float4*)&con[pp][k4];
            acc[pp] += cv.x * w0 + cv.y * w1 + cv.z * w2 + cv.w * w3;
        }
    }
#pragma unroll
    for (int pp = 0; pp < 32; pp++) {
        float v = acc[pp];
        v = v > 0.f ? v : expm1f(v);
        out[((size_t)b * HW + p0 + pp) * DD + d] = v;
    }
}

// ---------------- launch ----------------
extern "C" void kernel_launch(void* const* d_in, const int* in_sizes, int n_in,
                              void* d_out, int out_size) {
    const float* g    = (const float*)d_in[0];
    const float* mask = (const float*)d_in[1];
    const float* Wm   = (const float*)d_in[2];
    const float* bias = (const float*)d_in[3];
    float* out = (float*)d_out;

    k_prep1<<<NB * HW, 128>>>(g, mask);
    k_prep2<<<NB, 256>>>(mask);
    k_gemm1<<<dim3(25, 25, NB), 128>>>(g);
    k3_softmax<<<NB * HW, 256>>>();
    k4_buildT<<<NB * HW, 256>>>();
    k_gemm2<<<dim3(25, NB), 256>>>();
    k5_final<<<NB * 50, 128>>>(g, mask, Wm, bias, out);
}

// round 3
// speedup vs baseline: 1.1625x; 1.1625x over previous
#include <cuda_runtime.h>
#include <math.h>

#define NB 8
#define DD 128
#define HW 1600
#define CC 1444
#define CAS 1728          // padded CA row stride: 64 guard + 1600 (40x40) + 64 guard
#define CAOFF 64
#define KS 4              // gemm2 k-split

typedef unsigned long long ull;

// -------- scratch (static device arrays; no allocs allowed) --------
__device__ __align__(16) float d_bg[NB * HW * DD];            //  6.6 MB
__device__ __align__(16) float d_M[NB * HW * HW];             // 81.9 MB
__device__ __align__(16) float d_CApad[NB * HW * CAS];        // 88.5 MB
__device__ __align__(16) float d_T[NB * HW * HW];             // 81.9 MB
__device__ __align__(16) float d_Y4[KS * NB * HW * DD];       // 26.2 MB
__device__ float d_ng[NB * HW];
__device__ float d_k1d[NB * CC];
__device__ float d_wwd[NB * HW];
__device__ float d_zrowM[HW];        // stays zero (never written)
__device__ float d_zrowCA[CAS];      // stays zero (never written)

#define FMA2(acc, a, b) asm("fma.rn.f32x2 %0, %1, %2, %0;" : "+l"(acc) : "l"(a), "l"(b))
#define PACKD(dst, x)   asm("mov.b64 %0, {%1, %1};" : "=l"(dst) : "f"(x))
#define UNPK(lo, hi, v) asm("mov.b64 {%0, %1}, %2;" : "=f"(lo), "=f"(hi) : "l"(v))

__device__ __constant__ int OY9[9] = {-1,-1,-1, 0,0,0, 1,1,1};
__device__ __constant__ int OX9[9] = {-1, 0, 1,-1,0,1,-1,0,1};
// OFFL[k] = OY*40+OX
__device__ __constant__ int OFFL9[9] = {-41,-40,-39,-1,0,1,39,40,41};

// ---------------- prep1: bg = g*m, per-pixel |g|^2 ----------------
__global__ __launch_bounds__(128) void k_prep1(const float* __restrict__ g,
                                               const float* __restrict__ mask) {
    int p = blockIdx.x;
    int d = threadIdx.x;
    size_t gi = (size_t)p * DD + d;
    float gv = g[gi];
    float m = mask[p];
    d_bg[gi] = gv * m;
    float s = gv * gv;
#pragma unroll
    for (int o = 16; o; o >>= 1) s += __shfl_xor_sync(0xffffffffu, s, o);
    __shared__ float red[4];
    if ((d & 31) == 0) red[d >> 5] = s;
    __syncthreads();
    if (d == 0) d_ng[p] = red[0] + red[1] + red[2] + red[3];
}

// ---------------- prep2: k1d, wwd ----------------
__global__ __launch_bounds__(256) void k_prep2(const float* __restrict__ mask) {
    int b = blockIdx.x;
    __shared__ float ng[HW];
    __shared__ float ms[HW];
    for (int i = threadIdx.x; i < HW; i += 256) {
        ng[i] = d_ng[b * HW + i];
        ms[i] = mask[b * HW + i];
    }
    __syncthreads();
    for (int c = threadIdx.x; c < CC; c += 256) {
        int i = c / 38, j = c - i * 38;
        float s = 0.f;
#pragma unroll
        for (int dy = 0; dy < 3; dy++)
#pragma unroll
            for (int dx = 0; dx < 3; dx++) {
                int q = (i + dy) * 40 + (j + dx);
                s += ng[q] * ms[q];
            }
        d_k1d[b * CC + c] = s;
    }
    for (int l = threadIdx.x; l < HW; l += 256) {
        int y = l / 40, x = l - y * 40;
        float s = 0.f;
#pragma unroll
        for (int oy = -1; oy <= 1; oy++)
#pragma unroll
            for (int ox = -1; ox <= 1; ox++) {
                int yy = y + oy, xx = x + ox;
                if (yy >= 0 && yy < 40 && xx >= 0 && xx < 40) s += ng[yy * 40 + xx];
            }
        d_wwd[b * HW + l] = s;
    }
}

// ---------------- GEMM1: M = g @ bg^T (1600x1600, K=128) ----------------
// 64x64 tile, 64 threads, 8x8 microtile. A row-pairs natural, B duplicated.
__global__ __launch_bounds__(64) void k_gemm1(const float* __restrict__ g) {
    int b = blockIdx.z;
    int bx = blockIdx.x, by = blockIdx.y;
    __shared__ float As[16][64];   // [k][m-row]
    __shared__ ull Bd[16][64];     // [k][n-col] duplicated
    const float* A = g + ((size_t)b * HW + by * 64) * DD;
    const float* B = d_bg + ((size_t)b * HW + bx * 64) * DD;
    int t = threadIdx.x;
    int r0 = (t >> 3) * 8, c0 = (t & 7) * 8;

    ull acc[4][8];
#pragma unroll
    for (int i = 0; i < 4; i++)
#pragma unroll
        for (int j = 0; j < 8; j++) acc[i][j] = 0ull;

    for (int k0 = 0; k0 < DD; k0 += 16) {
        float4 a[4], bb[4];
#pragma unroll
        for (int s = 0; s < 4; s++) {
            a[s]  = *(const float4*)(A + (size_t)t * DD + k0 + s * 4);
            bb[s] = *(const float4*)(B + (size_t)t * DD + k0 + s * 4);
        }
        __syncthreads();
#pragma unroll
        for (int s = 0; s < 4; s++) {
            As[s * 4 + 0][t] = a[s].x; As[s * 4 + 1][t] = a[s].y;
            As[s * 4 + 2][t] = a[s].z; As[s * 4 + 3][t] = a[s].w;
            ull pv;
            PACKD(pv, bb[s].x); Bd[s * 4 + 0][t] = pv;
            PACKD(pv, bb[s].y); Bd[s * 4 + 1][t] = pv;
            PACKD(pv, bb[s].z); Bd[s * 4 + 2][t] = pv;
            PACKD(pv, bb[s].w); Bd[s * 4 + 3][t] = pv;
        }
        __syncthreads();
#pragma unroll
        for (int kk = 0; kk < 16; kk++) {
            ulonglong2 ap0 = *(const ulonglong2*)&As[kk][r0];
            ulonglong2 ap1 = *(const ulonglong2*)&As[kk][r0 + 4];
            ulonglong2 b0 = *(const ulonglong2*)&Bd[kk][c0];
            ulonglong2 b1 = *(const ulonglong2*)&Bd[kk][c0 + 2];
            ulonglong2 b2 = *(const ulonglong2*)&Bd[kk][c0 + 4];
            ulonglong2 b3 = *(const ulonglong2*)&Bd[kk][c0 + 6];
            ull ap[4] = {ap0.x, ap0.y, ap1.x, ap1.y};
            ull bp[8] = {b0.x, b0.y, b1.x, b1.y, b2.x, b2.y, b3.x, b3.y};
#pragma unroll
            for (int i = 0; i < 4; i++)
#pragma unroll
                for (int j = 0; j < 8; j++) FMA2(acc[i][j], ap[i], bp[j]);
        }
    }
    float* Mo = d_M + (size_t)b * HW * HW;
    int col = bx * 64 + c0;
#pragma unroll
    for (int i = 0; i < 4; i++) {
        float lo[8], hi[8];
#pragma unroll
        for (int j = 0; j < 8; j++) UNPK(lo[j], hi[j], acc[i][j]);
        int row = by * 64 + r0 + 2 * i;
        *(float4*)&Mo[(size_t)row * HW + col]           = make_float4(lo[0], lo[1], lo[2], lo[3]);
        *(float4*)&Mo[(size_t)row * HW + col + 4]       = make_float4(lo[4], lo[5], lo[6], lo[7]);
        *(float4*)&Mo[(size_t)(row + 1) * HW + col]     = make_float4(hi[0], hi[1], hi[2], hi[3]);
        *(float4*)&Mo[(size_t)(row + 1) * HW + col + 4] = make_float4(hi[4], hi[5], hi[6], hi[7]);
    }
}

// ---------------- block reduction (sum) ----------------
__device__ __forceinline__ float bsum(float v, volatile float* red) {
#pragma unroll
    for (int o = 16; o; o >>= 1) v += __shfl_xor_sync(0xffffffffu, v, o);
    int lane = threadIdx.x & 31;
    if (lane == 0) red[threadIdx.x >> 5] = v;
    __syncthreads();
    if (threadIdx.x < 32) {
        v = (lane < 8) ? red[lane] : 0.f;
#pragma unroll
        for (int o = 4; o; o >>= 1) v += __shfl_xor_sync(0xffffffffu, v, o);
        if (lane == 0) red[0] = v;
    }
    __syncthreads();
    float r = red[0];
    __syncthreads();
    return r;
}

// ---------------- k3: gather cs from M, distances, softmax -> padded CA ----------------
__global__ __launch_bounds__(256) void k3_softmax() {
    int b = blockIdx.x / HW;
    int loc = blockIdx.x - b * HW;
    int py = loc / 40, px = loc - py * 40;
    int tid = threadIdx.x;
    __shared__ float sh_e[CC];
    __shared__ float red[8];

    const float* Mb = d_M + (size_t)b * HW * HW;
    const float* rows[9];
#pragma unroll
    for (int k = 0; k < 9; k++) {
        int y = py + OY9[k], x = px + OX9[k];
        bool v = (y >= 0 && y < 40 && x >= 0 && x < 40);
        rows[k] = v ? (Mb + (size_t)(y * 40 + x) * HW) : d_zrowM;
    }
    float wwd = d_wwd[b * HW + loc];
    const float* k1 = d_k1d + b * CC;

    float dsr[6];
    float s = 0.f;
#pragma unroll
    for (int e = 0; e < 6; e++) {
        int c = tid + 256 * e;
        int cc = c < CC ? c : CC - 1;
        int i = cc / 38, j = cc - i * 38;
        int base = (i + 1) * 40 + (j + 1);
        float cs = 0.f;
#pragma unroll
        for (int k = 0; k < 9; k++) cs += rows[k][base + OFFL9[k]];
        float dv = k1[cc] + wwd - 2.f * cs;
        dsr[e] = dv;
        if (c < CC) s += dv;
    }
    float mu = bsum(s, red) * (1.f / CC);

    float s2 = 0.f;
#pragma unroll
    for (int e = 0; e < 6; e++) {
        int c = tid + 256 * e;
        if (c < CC) { float dd = dsr[e] - mu; s2 += dd * dd; }
    }
    float sd = sqrtf(bsum(s2, red) * (1.f / CC));
    float inv = 1.f / sd;

    // e = exp(-50*tanh(z) - 50), with tanh via exp(-2|z|):
    //   z>=0: exp(-100/(1+ex));  z<0: exp(-100*ex/(1+ex))
    float es = 0.f;
#pragma unroll
    for (int e = 0; e < 6; e++) {
        int c = tid + 256 * e;
        float z = (dsr[e] - mu) * inv;
        float a = fabsf(z);
        float ex = __expf(-2.f * a);
        float num = (z >= 0.f) ? 100.f : 100.f * ex;
        float ev = __expf(-__fdividef(num, 1.f + ex));
        if (c < CC) { sh_e[c] = ev; es += ev; }
    }
    float itot = 1.f / bsum(es, red);

    // write padded row (guards + zero borders + interior)
    float* car = d_CApad + (size_t)(b * HW + loc) * CAS;
    for (int idx = tid; idx < CAS; idx += 256) {
        int q = idx - CAOFF;
        float val = 0.f;
        if ((unsigned)q < (unsigned)HW) {
            int qy = q / 40, qx = q - qy * 40;
            if (qy >= 1 && qy <= 38 && qx >= 1 && qx <= 38)
                val = sh_e[(qy - 1) * 38 + (qx - 1)] * itot;
        }
        car[idx] = val;
    }
}

// ---------------- k4: T[p][q] = sum_k CApad[p-off_k][CAOFF + q - offl_k] ----------------
__global__ __launch_bounds__(256) void k4_buildT() {
    int b = blockIdx.x / HW;
    int p = blockIdx.x - b * HW;
    int py = p / 40, px = p - py * 40;
    const float* cab = d_CApad + (size_t)b * HW * CAS;
    const float* rows[9];
#pragma unroll
    for (int k = 0; k < 9; k++) {
        int ly = py - OY9[k], lx = px - OX9[k];
        bool v = (ly >= 0 && ly < 40 && lx >= 0 && lx < 40);
        rows[k] = v ? (cab + (size_t)(ly * 40 + lx) * CAS) : d_zrowCA;
    }
    float* trow = d_T + ((size_t)b * HW + p) * HW;
    for (int q = threadIdx.x; q < HW; q += 256) {
        float tsum = 0.f;
#pragma unroll
        for (int k = 0; k < 9; k++) tsum += rows[k][CAOFF + q - OFFL9[k]];
        trow[q] = tsum;
    }
}

// ---------------- GEMM2: Y = T @ bg (1600x128, K=1600), 4-way K-split ----------------
// tile M=64, N=128, 128 threads, 8x8 microtile. B col-pairs natural, A duplicated.
__global__ __launch_bounds__(128) void k_gemm2() {
    int b = blockIdx.z;
    int bx = blockIdx.x;          // p tile 0..24
    int ks = blockIdx.y;          // k split 0..3
    __shared__ ull Tsd[16][64];   // [k][p-row] duplicated
    __shared__ float Bs[16][128];
    const float* Trow = d_T + (size_t)b * HW * HW + (size_t)(bx * 64) * HW;
    const float* Bg = d_bg + (size_t)b * HW * DD;
    int t = threadIdx.x;
    int r0 = (t >> 4) * 8, c0 = (t & 15) * 8;
    int trl = t >> 1, tseg = (t & 1) * 8;        // T load: row 0..63, k-seg
    int bkr = t >> 3, bd0 = (t & 7) * 16;        // B load: k-row 0..15, d base

    ull acc[8][4];
#pragma unroll
    for (int i = 0; i < 8; i++)
#pragma unroll
        for (int j = 0; j < 4; j++) acc[i][j] = 0ull;

    int kbeg = ks * (HW / KS), kend = kbeg + HW / KS;
    for (int k0 = kbeg; k0 < kend; k0 += 16) {
        float4 t0 = *(const float4*)(Trow + (size_t)trl * HW + k0 + tseg);
        float4 t1 = *(const float4*)(Trow + (size_t)trl * HW + k0 + tseg + 4);
        float4 bv[4];
#pragma unroll
        for (int s = 0; s < 4; s++)
            bv[s] = *(const float4*)(Bg + (size_t)(k0 + bkr) * DD + bd0 + s * 4);
        __syncthreads();
        ull pv;
        PACKD(pv, t0.x); Tsd[tseg + 0][trl] = pv;
        PACKD(pv, t0.y); Tsd[tseg + 1][trl] = pv;
        PACKD(pv, t0.z); Tsd[tseg + 2][trl] = pv;
        PACKD(pv, t0.w); Tsd[tseg + 3][trl] = pv;
        PACKD(pv, t1.x); Tsd[tseg + 4][trl] = pv;
        PACKD(pv, t1.y); Tsd[tseg + 5][trl] = pv;
        PACKD(pv, t1.z); Tsd[tseg + 6][trl] = pv;
        PACKD(pv, t1.w); Tsd[tseg + 7][trl] = pv;
#pragma unroll
        for (int s = 0; s < 4; s++)
            *(float4*)&Bs[bkr][bd0 + s * 4] = bv[s];
        __syncthreads();
#pragma unroll
        for (int kk = 0; kk < 16; kk++) {
            ulonglong2 a0 = *(const ulonglong2*)&Tsd[kk][r0];
            ulonglong2 a1 = *(const ulonglong2*)&Tsd[kk][r0 + 2];
            ulonglong2 a2 = *(const ulonglong2*)&Tsd[kk][r0 + 4];
            ulonglong2 a3 = *(const ulonglong2*)&Tsd[kk][r0 + 6];
            ulonglong2 b0 = *(const ulonglong2*)&Bs[kk][c0];
            ulonglong2 b1 = *(const ulonglong2*)&Bs[kk][c0 + 4];
            ull ap[8] = {a0.x, a0.y, a1.x, a1.y, a2.x, a2.y, a3.x, a3.y};
            ull bp[4] = {b0.x, b0.y, b1.x, b1.y};
#pragma unroll
            for (int i = 0; i < 8; i++)
#pragma unroll
                for (int j = 0; j < 4; j++) FMA2(acc[i][j], ap[i], bp[j]);
        }
    }
    float* Yo = d_Y4 + (size_t)ks * NB * HW * DD + (size_t)b * HW * DD;
#pragma unroll
    for (int i = 0; i < 8; i++) {
        float lo[4], hi[4];
#pragma unroll
        for (int j = 0; j < 4; j++) UNPK(lo[j], hi[j], acc[i][j]);
        int row = bx * 64 + r0 + i;
        *(float4*)&Yo[(size_t)row * DD + c0]     = make_float4(lo[0], hi[0], lo[1], hi[1]);
        *(float4*)&Yo[(size_t)row * DD + c0 + 4] = make_float4(lo[2], hi[2], lo[3], hi[3]);
    }
}

// ---------------- k5: acl combine + concat + 1x1 conv + ELU ----------------
__global__ __launch_bounds__(128) void k5_final(const float* __restrict__ g,
                                                const float* __restrict__ mask,
                                                const float* __restrict__ Wm,
                                                const float* __restrict__ bias,
                                                float* __restrict__ out) {
    int b = blockIdx.x / 50;
    int p0 = (blockIdx.x % 50) * 32;
    int d = threadIdx.x;
    __shared__ float con[32][256];
    const size_t YSTR = (size_t)NB * HW * DD;

    for (int pp = 0; pp < 32; pp++) {
        int p = p0 + pp;
        size_t gi = ((size_t)b * HW + p) * DD + d;
        float gv = g[gi];
        float m = mask[b * HW + p];
        float ys = d_Y4[gi] + d_Y4[YSTR + gi] + d_Y4[2 * YSTR + gi] + d_Y4[3 * YSTR + gi];
        float acl = d_bg[gi] + (ys * (1.f / 9.f)) * (1.f - m);
        con[pp][d] = gv;
        con[pp][128 + d] = acl;
    }
    __syncthreads();

    float acc[32];
    float bv = bias[d];
#pragma unroll
    for (int pp = 0; pp < 32; pp++) acc[pp] = bv;

    for (int k4 = 0; k4 < 256; k4 += 4) {
        float w0 = Wm[(k4 + 0) * DD + d];
        float w1 = Wm[(k4 + 1) * DD + d];
        float w2 = Wm[(k4 + 2) * DD + d];
        float w3 = Wm[(k4 + 3) * DD + d];
#pragma unroll
        for (int pp = 0; pp < 32; pp++) {
            float4 cv = *(const float4*)&con[pp][k4];
            acc[pp] += cv.x * w0 + cv.y * w1 + cv.z * w2 + cv.w * w3;
        }
    }
#pragma unroll
    for (int pp = 0; pp < 32; pp++) {
        float v = acc[pp];
        v = v > 0.f ? v : expm1f(v);
        out[((size_t)b * HW + p0 + pp) * DD + d] = v;
    }
}

// ---------------- launch ----------------
extern "C" void kernel_launch(void* const* d_in, const int* in_sizes, int n_in,
                              void* d_out, int out_size) {
    const float* g    = (const float*)d_in[0];
    const float* mask = (const float*)d_in[1];
    const float* Wm   = (const float*)d_in[2];
    const float* bias = (const float*)d_in[3];
    float* out = (float*)d_out;

    k_prep1<<<NB * HW, 128>>>(g, mask);
    k_prep2<<<NB, 256>>>(mask);
    k_gemm1<<<dim3(25, 25, NB), 64>>>(g);
    k3_softmax<<<NB * HW, 256>>>();
    k4_buildT<<<NB * HW, 256>>>();
    k_gemm2<<<dim3(25, KS, NB), 128>>>();
    k5_final<<<NB * 50, 128>>>(g, mask, Wm, bias, out);
}

// round 5
// speedup vs baseline: 2.4093x; 2.0726x over previous
#include <cuda_runtime.h>
#include <cuda_bf16.h>
#include <math.h>
#include <stdint.h>

#define NB 8
#define DD 128
#define HW 1600
#define CC 1444
#define CAS 1728          // padded CA row stride
#define CAOFF 64
#define PAD 1664          // 13 * 128
#define MT 13
#define NSPLIT 8          // gemm2 k-split count

typedef unsigned long long ull;
typedef __nv_bfloat16 bf16;

// -------- scratch (static device arrays, zero-initialized at load) --------
__device__ __align__(16) float d_bg[NB * HW * DD];                    //  6.6 MB
__device__ __align__(16) float d_M[(size_t)NB * HW * HW];             // 81.9 MB
__device__ __align__(16) float d_CApad[(size_t)NB * HW * CAS];        // 88.5 MB
__device__ __align__(16) bf16 d_ghi[NB * PAD * DD];
__device__ __align__(16) bf16 d_glo[NB * PAD * DD];
__device__ __align__(16) bf16 d_bghi[NB * PAD * DD];
__device__ __align__(16) bf16 d_bglo[NB * PAD * DD];
__device__ __align__(16) bf16 d_bgThi[NB * DD * PAD];
__device__ __align__(16) bf16 d_bgTlo[NB * DD * PAD];
__device__ __align__(16) bf16 d_Thi[(size_t)NB * PAD * PAD];          // 44.3 MB
__device__ __align__(16) bf16 d_Tlo[(size_t)NB * PAD * PAD];          // 44.3 MB
__device__ __align__(16) float d_Y8[(size_t)NSPLIT * NB * HW * DD];   // 52.4 MB
__device__ float d_ng[NB * HW];
__device__ float d_k1d[NB * CC];
__device__ float d_wwd[NB * HW];
__device__ float d_zrowM[HW];        // stays zero
__device__ float d_zrowCA[CAS];      // stays zero
__device__ int d_tbase[CC];
__device__ int d_tpad[CAS];

__device__ __constant__ int OY9[9] = {-1,-1,-1, 0,0,0, 1,1,1};
__device__ __constant__ int OX9[9] = {-1, 0, 1,-1,0,1,-1,0,1};
__device__ __constant__ int OFFL9[9] = {-41,-40,-39,-1,0,1,39,40,41};

// ---------------- warp MMA helpers (plain PTX, no sm_100a features) ----------------
__device__ __forceinline__ uint32_t smem_u32(const void* p) {
    uint32_t a;
    asm("{ .reg .u64 t; cvta.to.shared.u64 t, %1; cvt.u32.u64 %0, t; }" : "=r"(a) : "l"(p));
    return a;
}

__device__ __forceinline__ void ldsm4(uint32_t& r0, uint32_t& r1, uint32_t& r2, uint32_t& r3,
                                      uint32_t addr) {
    asm volatile("ldmatrix.sync.aligned.m8n8.x4.shared.b16 {%0,%1,%2,%3}, [%4];"
                 : "=r"(r0), "=r"(r1), "=r"(r2), "=r"(r3) : "r"(addr));
}

__device__ __forceinline__ void mma16816(float* d, const uint32_t* a, uint32_t b0, uint32_t b1) {
    asm volatile("mma.sync.aligned.m16n8k16.row.col.f32.bf16.bf16.f32 "
                 "{%0,%1,%2,%3}, {%4,%5,%6,%7}, {%8,%9}, {%0,%1,%2,%3};"
                 : "+f"(d[0]), "+f"(d[1]), "+f"(d[2]), "+f"(d[3])
                 : "r"(a[0]), "r"(a[1]), "r"(a[2]), "r"(a[3]), "r"(b0), "r"(b1));
}

// smem tile: 128 rows x 40 bf16 (stride 40; 80B => conflict-free ldmatrix)
#define SSTR 40
#define BUFE (128 * SSTR)          // elements per buffer
#define BUFB (BUFE * 2)            // bytes per buffer (10240)

// core mainloop: accumulate 128x128 block tile; A/B K-major bf16 hi/lo
__device__ __forceinline__ void gemm_core(
    const bf16* __restrict__ Ah, const bf16* __restrict__ Al, int rsA,
    const bf16* __restrict__ Bh, const bf16* __restrict__ Bl, int rsB,
    int nChunks, float (&acc)[2][8][4], bf16* s, int tid)
{
    bf16* sAh = s;
    bf16* sAl = s + BUFE;
    bf16* sBh = s + 2 * BUFE;
    bf16* sBl = s + 3 * BUFE;
    uint32_t sb = smem_u32(s);
    int wid = tid >> 5, lane = tid & 31;
    int mbase = (wid & 3) * 32, nbase = (wid >> 2) * 64;
    int aro = (lane & 7) + ((lane >> 3) & 1) * 8;   // A: mats {r,r+8,r,r+8}
    int aco = (lane >> 4) * 8;                      //    cols {k,k,k+8,k+8}
    int bro = (lane & 7) + ((lane >> 4) & 1) * 8;   // B: mats {n,n,n+8,n+8}
    int bco = ((lane >> 3) & 1) * 8;                //    cols {k,k+8,k,k+8}

    for (int ch = 0; ch < nChunks; ch++) {
        __syncthreads();
        const bf16* pA = Ah + ch * 32;
        const bf16* pAl = Al + ch * 32;
        const bf16* pB = Bh + ch * 32;
        const bf16* pBl = Bl + ch * 32;
#pragma unroll
        for (int i = tid; i < 512; i += 256) {
            int r = i >> 2, c = (i & 3) * 8;
            *(uint4*)(sAh + r * SSTR + c) = *(const uint4*)(pA + (size_t)r * rsA + c);
            *(uint4*)(sAl + r * SSTR + c) = *(const uint4*)(pAl + (size_t)r * rsA + c);
            *(uint4*)(sBh + r * SSTR + c) = *(const uint4*)(pB + (size_t)r * rsB + c);
            *(uint4*)(sBl + r * SSTR + c) = *(const uint4*)(pBl + (size_t)r * rsB + c);
        }
        __syncthreads();
#pragma unroll
        for (int kk = 0; kk < 32; kk += 16) {
            uint32_t ah[2][4], al[2][4];
#pragma unroll
            for (int mi = 0; mi < 2; mi++) {
                uint32_t off = (uint32_t)(((mbase + mi * 16 + aro) * SSTR + kk + aco) * 2);
                ldsm4(ah[mi][0], ah[mi][1], ah[mi][2], ah[mi][3], sb + off);
                ldsm4(al[mi][0], al[mi][1], al[mi][2], al[mi][3], sb + BUFB + off);
            }
            uint32_t bh[4][4], bl[4][4];
#pragma unroll
            for (int ng = 0; ng < 4; ng++) {
                uint32_t off = (uint32_t)(((nbase + ng * 16 + bro) * SSTR + kk + bco) * 2);
                ldsm4(bh[ng][0], bh[ng][1], bh[ng][2], bh[ng][3], sb + 2 * BUFB + off);
                ldsm4(bl[ng][0], bl[ng][1], bl[ng][2], bl[ng][3], sb + 3 * BUFB + off);
            }
#pragma unroll
            for (int mi = 0; mi < 2; mi++)
#pragma unroll
                for (int nj = 0; nj < 8; nj++) {
                    int ng = nj >> 1;
                    uint32_t b0h = (nj & 1) ? bh[ng][2] : bh[ng][0];
                    uint32_t b1h = (nj & 1) ? bh[ng][3] : bh[ng][1];
                    uint32_t b0l = (nj & 1) ? bl[ng][2] : bl[ng][0];
                    uint32_t b1l = (nj & 1) ? bl[ng][3] : bl[ng][1];
                    mma16816(acc[mi][nj], ah[mi], b0h, b1h);
                    mma16816(acc[mi][nj], ah[mi], b0l, b1l);
                    mma16816(acc[mi][nj], al[mi], b0h, b1h);
                }
        }
    }
}

// ---------------- k_tab: index lookup tables ----------------
__global__ void k_tab() {
    int i = blockIdx.x * 256 + threadIdx.x;
    if (i < CC) d_tbase[i] = ((i / 38) + 1) * 40 + (i % 38) + 1;
    if (i < CAS) {
        int q = i - CAOFF;
        int v = -1;
        if (q >= 0 && q < HW) {
            int qy = q / 40, qx = q % 40;
            if (qy >= 1 && qy <= 38 && qx >= 1 && qx <= 38) v = (qy - 1) * 38 + (qx - 1);
        }
        d_tpad[i] = v;
    }
}

// ---------------- prep1: bg, bf16 splits, per-pixel |g|^2 ----------------
__global__ __launch_bounds__(128) void k_prep1(const float* __restrict__ g,
                                               const float* __restrict__ mask) {
    int p = blockIdx.x;
    int b = p / HW, r = p - b * HW;
    int d = threadIdx.x;
    size_t gi = (size_t)p * DD + d;
    float gv = g[gi];
    float m = mask[p];
    float bgv = gv * m;
    d_bg[gi] = bgv;
    size_t pi = ((size_t)b * PAD + r) * DD + d;
    bf16 gh = __float2bfloat16(gv);
    bf16 gl = __float2bfloat16(gv - __bfloat162float(gh));
    bf16 bh = __float2bfloat16(bgv);
    bf16 bl = __float2bfloat16(bgv - __bfloat162float(bh));
    d_ghi[pi] = gh; d_glo[pi] = gl;
    d_bghi[pi] = bh; d_bglo[pi] = bl;
    float s = gv * gv;
#pragma unroll
    for (int o = 16; o; o >>= 1) s += __shfl_xor_sync(0xffffffffu, s, o);
    __shared__ float red[4];
    if ((d & 31) == 0) red[d >> 5] = s;
    __syncthreads();
    if (d == 0) d_ng[p] = red[0] + red[1] + red[2] + red[3];
}

// ---------------- prep2: k1d, wwd ----------------
__global__ __launch_bounds__(256) void k_prep2(const float* __restrict__ mask) {
    int b = blockIdx.x;
    __shared__ float ng[HW];
    __shared__ float ms[HW];
    for (int i = threadIdx.x; i < HW; i += 256) {
        ng[i] = d_ng[b * HW + i];
        ms[i] = mask[b * HW + i];
    }
    __syncthreads();
    for (int c = threadIdx.x; c < CC; c += 256) {
        int i = c / 38, j = c - i * 38;
        float s = 0.f;
#pragma unroll
        for (int dy = 0; dy < 3; dy++)
#pragma unroll
            for (int dx = 0; dx < 3; dx++) {
                int q = (i + dy) * 40 + (j + dx);
                s += ng[q] * ms[q];
            }
        d_k1d[b * CC + c] = s;
    }
    for (int l = threadIdx.x; l < HW; l += 256) {
        int y = l / 40, x = l - y * 40;
        float s = 0.f;
#pragma unroll
        for (int oy = -1; oy <= 1; oy++)
#pragma unroll
            for (int ox = -1; ox <= 1; ox++) {
                int yy = y + oy, xx = x + ox;
                if (yy >= 0 && yy < 40 && xx >= 0 && xx < 40) s += ng[yy * 40 + xx];
            }
        d_wwd[b * HW + l] = s;
    }
}

// ---------------- prepT: bgT[d][q] = bg[q][d] (bf16 hi/lo, padded q) ----------------
__global__ __launch_bounds__(256) void k_prepT() {
    int b = blockIdx.y;
    int q0 = blockIdx.x * 64;
    __shared__ bf16 shi[64][DD + 2], slo[64][DD + 2];
    int tid = threadIdx.x;
    for (int i = tid; i < 64 * DD; i += 256) {
        int qq = i >> 7, dc = i & 127;
        int q = q0 + qq;
        bf16 h = __float2bfloat16(0.f), l = h;
        if (q < HW) {
            size_t src = ((size_t)b * PAD + q) * DD + dc;
            h = d_bghi[src]; l = d_bglo[src];
        }
        shi[qq][dc] = h; slo[qq][dc] = l;
    }
    __syncthreads();
    for (int i = tid; i < DD * 64; i += 256) {
        int dr = i >> 6, qq = i & 63;
        size_t dst = ((size_t)b * DD + dr) * PAD + q0 + qq;
        d_bgThi[dst] = shi[qq][dr];
        d_bgTlo[dst] = slo[qq][dr];
    }
}

// ---------------- GEMM1 (mma.sync): M = g @ bg^T ----------------
__global__ __launch_bounds__(256) void k_gemm1_mma() {
    __shared__ bf16 smem[4 * BUFE];
    int b = blockIdx.z, nt = blockIdx.x, mt = blockIdx.y;
    int tid = threadIdx.x;
    float acc[2][8][4];
#pragma unroll
    for (int i = 0; i < 2; i++)
#pragma unroll
        for (int j = 0; j < 8; j++)
#pragma unroll
            for (int k = 0; k < 4; k++) acc[i][j][k] = 0.f;

    const bf16* Ah = d_ghi + ((size_t)b * PAD + mt * 128) * DD;
    const bf16* Al = d_glo + ((size_t)b * PAD + mt * 128) * DD;
    const bf16* Bh = d_bghi + ((size_t)b * PAD + nt * 128) * DD;
    const bf16* Bl = d_bglo + ((size_t)b * PAD + nt * 128) * DD;
    gemm_core(Ah, Al, DD, Bh, Bl, DD, 4, acc, smem, tid);

    int wid = tid >> 5, lane = tid & 31;
    int mw = (wid & 3) * 32, nw = (wid >> 2) * 64;
    float* Mo = d_M + (size_t)b * HW * HW;
#pragma unroll
    for (int mi = 0; mi < 2; mi++)
#pragma unroll
        for (int nj = 0; nj < 8; nj++) {
            int m0 = mt * 128 + mw + mi * 16 + (lane >> 2);
            int n = nt * 128 + nw + nj * 8 + (lane & 3) * 2;
            if (n < HW) {
                if (m0 < HW) *(float2*)&Mo[(size_t)m0 * HW + n] = make_float2(acc[mi][nj][0], acc[mi][nj][1]);
                if (m0 + 8 < HW) *(float2*)&Mo[(size_t)(m0 + 8) * HW + n] = make_float2(acc[mi][nj][2], acc[mi][nj][3]);
            }
        }
}

// ---------------- block reduction (sum) ----------------
__device__ __forceinline__ float bsum(float v, volatile float* red) {
#pragma unroll
    for (int o = 16; o; o >>= 1) v += __shfl_xor_sync(0xffffffffu, v, o);
    int lane = threadIdx.x & 31;
    if (lane == 0) red[threadIdx.x >> 5] = v;
    __syncthreads();
    if (threadIdx.x < 32) {
        v = (lane < 8) ? red[lane] : 0.f;
#pragma unroll
        for (int o = 4; o; o >>= 1) v += __shfl_xor_sync(0xffffffffu, v, o);
        if (lane == 0) red[0] = v;
    }
    __syncthreads();
    float r = red[0];
    __syncthreads();
    return r;
}

// ---------------- k3: gather cs from M, distances, softmax -> padded CA ----------------
__global__ __launch_bounds__(256) void k3_softmax() {
    int b = blockIdx.x / HW;
    int loc = blockIdx.x - b * HW;
    int py = loc / 40, px = loc - py * 40;
    int tid = threadIdx.x;
    __shared__ float sh_e[CC];
    __shared__ float red[8];

    const float* Mb = d_M + (size_t)b * HW * HW;
    const float* rows[9];
#pragma unroll
    for (int k = 0; k < 9; k++) {
        int y = py + OY9[k], x = px + OX9[k];
        bool v = (y >= 0 && y < 40 && x >= 0 && x < 40);
        rows[k] = v ? (Mb + (size_t)(y * 40 + x) * HW) : d_zrowM;
    }
    float wwd = d_wwd[b * HW + loc];
    const float* k1 = d_k1d + b * CC;

    float dsr[6];
    float s = 0.f;
#pragma unroll
    for (int e = 0; e < 6; e++) {
        int c = tid + 256 * e;
        int cc = c < CC ? c : CC - 1;
        int base = d_tbase[cc];
        float cs = 0.f;
#pragma unroll
        for (int k = 0; k < 9; k++) cs += rows[k][base + OFFL9[k]];
        float dv = k1[cc] + wwd - 2.f * cs;
        dsr[e] = dv;
        if (c < CC) s += dv;
    }
    float mu = bsum(s, red) * (1.f / CC);

    float s2 = 0.f;
#pragma unroll
    for (int e = 0; e < 6; e++) {
        int c = tid + 256 * e;
        if (c < CC) { float dd = dsr[e] - mu; s2 += dd * dd; }
    }
    float sd = sqrtf(bsum(s2, red) * (1.f / CC));
    float inv = 1.f / sd;

    // e = exp(-50*tanh(z) - 50) via exp(-2|z|)
    float es = 0.f;
#pragma unroll
    for (int e = 0; e < 6; e++) {
        int c = tid + 256 * e;
        float z = (dsr[e] - mu) * inv;
        float a = fabsf(z);
        float ex = __expf(-2.f * a);
        float num = (z >= 0.f) ? 100.f : 100.f * ex;
        float ev = __expf(-__fdividef(num, 1.f + ex));
        if (c < CC) { sh_e[c] = ev; es += ev; }
    }
    float itot = 1.f / bsum(es, red);

    float* car = d_CApad + (size_t)(b * HW + loc) * CAS;
    for (int idx = tid; idx < CAS; idx += 256) {
        int sidx = d_tpad[idx];
        car[idx] = (sidx >= 0) ? sh_e[sidx] * itot : 0.f;
    }
}

// ---------------- k4: T (bf16 hi/lo, padded) ----------------
__global__ __launch_bounds__(256) void k4_buildT() {
    int b = blockIdx.x / HW;
    int p = blockIdx.x - b * HW;
    int py = p / 40, px = p - py * 40;
    const float* cab = d_CApad + (size_t)b * HW * CAS;
    const float* rows[9];
#pragma unroll
    for (int k = 0; k < 9; k++) {
        int ly = py - OY9[k], lx = px - OX9[k];
        bool v = (ly >= 0 && ly < 40 && lx >= 0 && lx < 40);
        rows[k] = v ? (cab + (size_t)(ly * 40 + lx) * CAS) : d_zrowCA;
    }
    size_t tbase = ((size_t)b * PAD + p) * PAD;
    for (int q = threadIdx.x; q < HW; q += 256) {
        float tsum = 0.f;
#pragma unroll
        for (int k = 0; k < 9; k++) tsum += rows[k][CAOFF + q - OFFL9[k]];
        bf16 h = __float2bfloat16(tsum);
        bf16 l = __float2bfloat16(tsum - __bfloat162float(h));
        d_Thi[tbase + q] = h;
        d_Tlo[tbase + q] = l;
    }
    if (threadIdx.x < PAD - HW) {
        bf16 z = __float2bfloat16(0.f);
        d_Thi[tbase + HW + threadIdx.x] = z;
        d_Tlo[tbase + HW + threadIdx.x] = z;
    }
}

// ---------------- GEMM2 (mma.sync): Y = T @ bg, 8-way K-split ----------------
// chunks of 32 along K (q): 50 chunks total; split s gets {7,7,6,6,6,6,6,6}
__global__ __launch_bounds__(256) void k_gemm2_mma() {
    __shared__ bf16 smem[4 * BUFE];
    int b = blockIdx.z, mt = blockIdx.x, s = blockIdx.y;
    int tid = threadIdx.x;
    int kc0 = (s < 2) ? 7 * s : 14 + 6 * (s - 2);
    int nch = (s < 2) ? 7 : 6;

    float acc[2][8][4];
#pragma unroll
    for (int i = 0; i < 2; i++)
#pragma unroll
        for (int j = 0; j < 8; j++)
#pragma unroll
            for (int k = 0; k < 4; k++) acc[i][j][k] = 0.f;

    const bf16* Ah = d_Thi + ((size_t)b * PAD + mt * 128) * PAD + kc0 * 32;
    const bf16* Al = d_Tlo + ((size_t)b * PAD + mt * 128) * PAD + kc0 * 32;
    const bf16* Bh = d_bgThi + (size_t)b * DD * PAD + kc0 * 32;
    const bf16* Bl = d_bgTlo + (size_t)b * DD * PAD + kc0 * 32;
    gemm_core(Ah, Al, PAD, Bh, Bl, PAD, nch, acc, smem, tid);

    int wid = tid >> 5, lane = tid & 31;
    int mw = (wid & 3) * 32, nw = (wid >> 2) * 64;
    float* Yo = d_Y8 + ((size_t)s * NB + b) * HW * DD;
#pragma unroll
    for (int mi = 0; mi < 2; mi++)
#pragma unroll
        for (int nj = 0; nj < 8; nj++) {
            int m0 = mt * 128 + mw + mi * 16 + (lane >> 2);
            int n = nw + nj * 8 + (lane & 3) * 2;   // n < 128 always
            if (m0 < HW) *(float2*)&Yo[(size_t)m0 * DD + n] = make_float2(acc[mi][nj][0], acc[mi][nj][1]);
            if (m0 + 8 < HW) *(float2*)&Yo[(size_t)(m0 + 8) * DD + n] = make_float2(acc[mi][nj][2], acc[mi][nj][3]);
        }
}

// ---------------- k5: acl combine + concat + 1x1 conv + ELU ----------------
__global__ __launch_bounds__(128) void k5_final(const float* __restrict__ g,
                                                const float* __restrict__ mask,
                                                const float* __restrict__ Wm,
                                                const float* __restrict__ bias,
                                                float* __restrict__ out) {
    int b = blockIdx.x / 50;
    int p0 = (blockIdx.x % 50) * 32;
    int d = threadIdx.x;
    __shared__ float con[32][256];
    const size_t YSTR = (size_t)NB * HW * DD;

    for (int pp = 0; pp < 32; pp++) {
        int p = p0 + pp;
        size_t gi = ((size_t)b * HW + p) * DD + d;
        float gv = g[gi];
        float m = mask[b * HW + p];
        float ys = 0.f;
#pragma unroll
        for (int s = 0; s < NSPLIT; s++) ys += d_Y8[s * YSTR + gi];
        float acl = d_bg[gi] + (ys * (1.f / 9.f)) * (1.f - m);
        con[pp][d] = gv;
        con[pp][128 + d] = acl;
    }
    __syncthreads();

    float acc[32];
    float bv = bias[d];
#pragma unroll
    for (int pp = 0; pp < 32; pp++) acc[pp] = bv;

    for (int k4i = 0; k4i < 256; k4i += 4) {
        float w0 = Wm[(k4i + 0) * DD + d];
        float w1 = Wm[(k4i + 1) * DD + d];
        float w2 = Wm[(k4i + 2) * DD + d];
        float w3 = Wm[(k4i + 3) * DD + d];
#pragma unroll
        for (int pp = 0; pp < 32; pp++) {
            float4 cv = *(const float4*)&con[pp][k4i];
            acc[pp] += cv.x * w0 + cv.y * w1 + cv.z * w2 + cv.w * w3;
        }
    }
#pragma unroll
    for (int pp = 0; pp < 32; pp++) {
        float v = acc[pp];
        v = v > 0.f ? v : expm1f(v);
        out[((size_t)b * HW + p0 + pp) * DD + d] = v;
    }
}

// ---------------- launch ----------------
extern "C" void kernel_launch(void* const* d_in, const int* in_sizes, int n_in,
                              void* d_out, int out_size) {
    const float* g    = (const float*)d_in[0];
    const float* mask = (const float*)d_in[1];
    const float* Wm   = (const float*)d_in[2];
    const float* bias = (const float*)d_in[3];
    float* out = (float*)d_out;

    k_tab<<<7, 256>>>();
    k_prep1<<<NB * HW, 128>>>(g, mask);
    k_prep2<<<NB, 256>>>(mask);
    k_prepT<<<dim3(PAD / 64, NB), 256>>>();
    k_gemm1_mma<<<dim3(MT, MT, NB), 256>>>();
    k3_softmax<<<NB * HW, 256>>>();
    k4_buildT<<<NB * HW, 256>>>();
    k_gemm2_mma<<<dim3(MT, NSPLIT, NB), 256>>>();
    k5_final<<<NB * 50, 128>>>(g, mask, Wm, bias, out);
}